// round 14
// baseline (speedup 1.0000x reference)
#include <cuda_runtime.h>
#include <cuda_bf16.h>

// S4 Vandermonde kernel: out[h,l] = 2*Re( sum_n Ceff[h,n] * w[h,n]^l )
//   w = exp(dtA), Ceff = Bc*Cc*(w-1)/A ;  H=512, NH=32, L=8192.
//
// R13 = R12 geometry and math EXACTLY, but every main-loop f32x2 op is cast
// into its DESTRUCTIVE (in-place) form to cut distinct register-pair counts:
//   RA <- Q*RA      (FMUL2 d==a : 2 pairs, rt2)   [was fresh-dst mul, rt3]
//   RA <- P*RB + RA (FFMA2 d==c : 3 pairs, rt3)   [was 4-pair fma,   rt4]
//   tree levels 2-4 accumulate in place (rt2)     [was rt3]
// RF-banking law: rt = max(rt_pipe, #even_distinct, #odd_distinct); 64-bit
// operands occupy both banks. Per-step floor 163 -> ~125 cyc. Rounding order
// is identical to R12 (mul rounded, fma fused).

#define HH 512
#define NHALF 32
#define LL 8192
#define SPT 64                       // recurrence steps per lane
#define WPB 4                        // warps per block
#define CHUNK (32 * SPT)             // 2048 l-values per warp
#define CHUNKS_PER_H (LL / CHUNK)    // 4

typedef unsigned long long u64;

__device__ __forceinline__ u64 pk2(float lo, float hi) {
    u64 r; asm("mov.b64 %0,{%1,%2};" : "=l"(r) : "f"(lo), "f"(hi)); return r;
}
__device__ __forceinline__ void upk2(u64 v, float& lo, float& hi) {
    asm("mov.b64 {%0,%1},%2;" : "=f"(lo), "=f"(hi) : "l"(v));
}
// fresh-destination add (first tree level): 3 distinct pairs
__device__ __forceinline__ u64 f2add(u64 a, u64 b) {
    u64 r; asm("add.rn.f32x2 %0,%1,%2;" : "=l"(r) : "l"(a), "l"(b)); return r;
}
// in-place accumulate: a += b (2 distinct pairs, rt2)
__device__ __forceinline__ void f2add_ip(u64& a, u64 b) {
    asm("add.rn.f32x2 %0,%0,%1;" : "+l"(a) : "l"(b));
}
// in-place scale: a *= b (2 distinct pairs, rt2)
__device__ __forceinline__ void f2mul_ip(u64& a, u64 b) {
    asm("mul.rn.f32x2 %0,%1,%0;" : "+l"(a) : "l"(b));
}
// in-place fma onto accumulator: d += a*b (3 distinct pairs, rt3)
__device__ __forceinline__ void f2fma_ip(u64& d, u64 a, u64 b) {
    asm("fma.rn.f32x2 %0,%1,%2,%0;" : "+l"(d) : "l"(a), "l"(b));
}

__device__ __forceinline__ float2 cmulf(float2 a, float2 b) {
    return make_float2(fmaf(a.x, b.x, -a.y * b.y), fmaf(a.x, b.y, a.y * b.x));
}

// reduction tree over 16 packed pairs -> scalar; level 1 fresh, rest in-place
__device__ __forceinline__ float sumtree16(const u64* R) {
    u64 s0 = f2add(R[0], R[8]);
    u64 s1 = f2add(R[1], R[9]);
    u64 s2 = f2add(R[2], R[10]);
    u64 s3 = f2add(R[3], R[11]);
    u64 s4 = f2add(R[4], R[12]);
    u64 s5 = f2add(R[5], R[13]);
    u64 s6 = f2add(R[6], R[14]);
    u64 s7 = f2add(R[7], R[15]);
    f2add_ip(s0, s4); f2add_ip(s1, s5);
    f2add_ip(s2, s6); f2add_ip(s3, s7);
    f2add_ip(s0, s2); f2add_ip(s1, s3);
    f2add_ip(s0, s1);
    float lo, hi; upk2(s0, lo, hi);
    return lo + hi;
}

#define PI2_HI 6.2831854820251465f
#define PI2_LO (-1.7484561e-7f)
#define INV2PI 0.15915494309189535f

// accurate sin/cos with two-float 2*pi reduction
__device__ __forceinline__ void redsc(float th, float* s, float* c) {
    float kk = rintf(th * INV2PI);
    float r  = fmaf(-kk, PI2_HI, th);
    r        = fmaf(-kk, PI2_LO, r);
    __sincosf(r, s, c);
}

// per-mode start values from the smem param rows at offset l0f
__device__ __forceinline__ void start_mode(const float4* mpn, float l0f,
                                           float& r0, float& rm,
                                           float& p,  float& q) {
    float4 a = mpn[0];   // p, q, wm32r, wm32i
    float4 b = mpn[1];   // c2r, c2i, dre, dim
    p = a.x; q = a.y;
    float sn, cs;
    redsc(b.w * l0f, &sn, &cs);          // theta = dim*l0 (same rounding as ref)
    float mg  = __expf(b.z * l0f);       // dre*l0 <= 0 -> mg <= 1
    float zr  = mg * cs, zi = mg * sn;
    float z0r = fmaf(b.x, zr, -b.y * zi);
    float z0i = fmaf(b.x, zi,  b.y * zr);
    r0 = z0r;                            // r(l0)
    rm = fmaf(z0r, a.z, -z0i * a.w);     // Re(z0 * w^-32) = r(l0-32)
}

__global__ void __launch_bounds__(128, 3)
s4_vandermonde_kernel(const float* __restrict__ log_dt,
                      const float* __restrict__ log_A_real,
                      const float* __restrict__ A_imag,
                      const float* __restrict__ Bmat,
                      const float* __restrict__ Cmat,
                      float* __restrict__ out)
{
    // per warp, per mode: row0 = {p, q, wm32r, wm32i}, row1 = {c2r, c2i, dre, dim}
    __shared__ float4 mp[WPB][NHALF][2];

    const int w   = threadIdx.x >> 5;
    const int j   = threadIdx.x & 31;
    const int gw  = blockIdx.x * WPB + w;
    const int h   = gw >> 2;       // / CHUNKS_PER_H
    const int chk = gw & 3;

    // ---------- phase A: lane j computes mode j params (MUFU-heavy) ----------
    {
        const int n = j;
        const float dt  = __expf(log_dt[h]);
        const float ar  = -__expf(log_A_real[h * NHALF + n]);
        const float aiv = -A_imag[h * NHALF + n];
        const float dre = dt * ar;
        const float dim = dt * aiv;

        // w^32 -> p, q; w^-32 (magnitude clamped; when clamped q underflowed to 0)
        float s32, c32; redsc(32.f * dim, &s32, &c32);
        float mg32 = __expf(32.f * dre);
        float w32r = mg32 * c32, w32i = mg32 * s32;
        float p = w32r + w32r;
        float q = -fmaf(w32r, w32r, w32i * w32i);
        float mgm = __expf(fminf(-32.f * dre, 60.f));
        float wmr = mgm * c32, wmi = -mgm * s32;
        // 2*Ceff = 2*Bc*Cc*(w^1 - 1)/A
        float s1v, c1v; redsc(dim, &s1v, &c1v);
        float mg1 = __expf(dre);
        float2 w1  = make_float2(mg1 * c1v, mg1 * s1v);
        float2 num = make_float2(w1.x - 1.0f, w1.y);
        float  inv = 2.0f / fmaf(ar, ar, aiv * aiv);
        float2 ia  = make_float2(ar * inv, -aiv * inv);
        const float2* Bv = (const float2*)Bmat;
        const float2* Cv = (const float2*)Cmat;
        float2 bc  = cmulf(Bv[h * NHALF + n], Cv[h * NHALF + n]);
        float2 c2  = cmulf(cmulf(bc, num), ia);

        mp[w][n][0] = make_float4(p, q, wmr, wmi);
        mp[w][n][1] = make_float4(c2.x, c2.y, dre, dim);
    }
    __syncwarp();

    // ---------- phase B: direct seed at l0 = chk*2048 + j ----------
    const float l0f = (float)(chk * CHUNK + j);
    u64 RB[NHALF / 2], RA[NHALF / 2], P[NHALF / 2], Q[NHALF / 2];
    #pragma unroll
    for (int m = 0; m < NHALF / 2; m++) {
        float r0a, rma, pa, qa, r0b, rmb, pb, qb;
        start_mode(&mp[w][2 * m][0],     l0f, r0a, rma, pa, qa);
        start_mode(&mp[w][2 * m + 1][0], l0f, r0b, rmb, pb, qb);
        RB[m] = pk2(r0a, r0b);        // r_0
        RA[m] = pk2(rma, rmb);        // r_-1
        P[m]  = pk2(pa, pb);
        Q[m]  = pk2(qa, qb);
    }

    // ---------- main recurrence: in-place ops, unrolled by 2 with role swap ----------
    float* op = out + h * LL + chk * CHUNK + j;
    #pragma unroll 4
    for (int i = 0; i < SPT; i += 2) {
        op[i * 32] = sumtree16(RB);                   // r_i
        #pragma unroll
        for (int m = 0; m < NHALF / 2; m++) {         // RA <- Q*RA + P*RB
            f2mul_ip(RA[m], Q[m]);                    // rt2
            f2fma_ip(RA[m], P[m], RB[m]);             // rt3
        }
        op[(i + 1) * 32] = sumtree16(RA);             // r_{i+1}
        #pragma unroll
        for (int m = 0; m < NHALF / 2; m++) {         // RB <- Q*RB + P*RA
            f2mul_ip(RB[m], Q[m]);
            f2fma_ip(RB[m], P[m], RA[m]);
        }
    }
}

extern "C" void kernel_launch(void* const* d_in, const int* in_sizes, int n_in,
                              void* d_out, int out_size)
{
    const float* log_dt     = (const float*)d_in[0];
    const float* log_A_real = (const float*)d_in[1];
    const float* A_imag     = (const float*)d_in[2];
    const float* Bmat       = (const float*)d_in[3];
    const float* Cmat       = (const float*)d_in[4];
    float* out = (float*)d_out;

    dim3 grid(HH * CHUNKS_PER_H / WPB);   // 512 blocks
    dim3 block(32 * WPB);                 // 128 threads
    s4_vandermonde_kernel<<<grid, block>>>(log_dt, log_A_real, A_imag,
                                           Bmat, Cmat, out);
}

// round 16
// speedup vs baseline: 1.7843x; 1.7843x over previous
#include <cuda_runtime.h>
#include <cuda_bf16.h>

// S4 Vandermonde kernel via warp-level bf16 mma.sync (standard PTX, sm_80+;
// avoids tcgen05 which the harness's ptxas target rejects).
//   out[h, 64a+b] = sum_k G[a,k] * V[b,k],   K = 64 (re/im of 32 modes)
//   G[a,2n]=Re(2Ceff_n w_n^{64a}), G[a,2n+1]=-Im(...),
//   V[b,2n]=Re(w_n^b),            V[b,2n+1]=Im(w_n^b)
// fp32 accuracy via Dekker bf16 splits: D = G1V1 + G1V2 + G2V1 (G2V2 <= 2^-18).
// Fragments are generated ANALYTICALLY in registers per lane (no smem tiles,
// no ldmatrix): m16n8k16.row.col layout -> lane(g=lid>>2, t=lid&3) needs
// A rows {g, g+8} / modes {t, t+4} (+8 per k-step), B cols b=8nt+g, same modes.
// One CTA per h; warp w owns output rows [32w, 32w+32).

typedef unsigned int u32;

#define HH 512
#define NH 32
#define LL 8192

#define PI2_HI 6.2831854820251465f
#define PI2_LO (-1.7484561e-7f)
#define INV2PI 0.15915494309189535f

__device__ __forceinline__ void redsc(float th, float* s, float* c) {
    float kk = rintf(th * INV2PI);
    float r  = fmaf(-kk, PI2_HI, th);
    r        = fmaf(-kk, PI2_LO, r);
    __sincosf(r, s, c);
}
__device__ __forceinline__ float2 cmulf(float2 a, float2 b) {
    return make_float2(fmaf(a.x, b.x, -a.y * b.y), fmaf(a.x, b.y, a.y * b.x));
}
// pack (x->low bf16, y->high bf16); return fp32 residuals of each half
__device__ __forceinline__ u32 pack_split(float x, float y, float& rx, float& ry) {
    u32 w; asm("cvt.rn.bf16x2.f32 %0, %1, %2;" : "=r"(w) : "f"(y), "f"(x));
    rx = x - __uint_as_float(w << 16);
    ry = y - __uint_as_float(w & 0xFFFF0000u);
    return w;
}
__device__ __forceinline__ u32 pack_only(float x, float y) {
    u32 w; asm("cvt.rn.bf16x2.f32 %0, %1, %2;" : "=r"(w) : "f"(y), "f"(x));
    return w;
}
// D += A*B, m16n8k16 bf16 -> f32
__device__ __forceinline__ void mma_bf16(float* c, u32 a0, u32 a1, u32 a2, u32 a3,
                                         u32 b0, u32 b1) {
    asm volatile(
        "mma.sync.aligned.m16n8k16.row.col.f32.bf16.bf16.f32 "
        "{%0,%1,%2,%3}, {%4,%5,%6,%7}, {%8,%9}, {%0,%1,%2,%3};"
        : "+f"(c[0]), "+f"(c[1]), "+f"(c[2]), "+f"(c[3])
        : "r"(a0), "r"(a1), "r"(a2), "r"(a3), "r"(b0), "r"(b1));
}

__global__ void __launch_bounds__(128, 3)
s4_mma_kernel(const float* __restrict__ log_dt,
              const float* __restrict__ log_A_real,
              const float* __restrict__ A_imag,
              const float* __restrict__ Bmat,
              const float* __restrict__ Cmat,
              float* __restrict__ out)
{
    __shared__ float4 prm[NH];   // {dre, dim, c2r, c2i}, c2 = 2*Ceff
    const int tid = threadIdx.x, wid = tid >> 5, lid = tid & 31;
    const int g = lid >> 2, t = lid & 3;
    const int h = blockIdx.x;

    // ---- mode params (warp 0, lane n) ----
    if (wid == 0) {
        const int n = lid;
        float dt  = __expf(log_dt[h]);
        float ar  = -__expf(log_A_real[h * NH + n]);
        float aiv = -A_imag[h * NH + n];
        float dre = dt * ar, dim = dt * aiv;
        float s1, c1; redsc(dim, &s1, &c1);
        float mg1 = __expf(dre);
        float2 w1  = make_float2(mg1 * c1, mg1 * s1);
        float2 num = make_float2(w1.x - 1.0f, w1.y);
        float  inv = 2.0f / fmaf(ar, ar, aiv * aiv);
        float2 ia  = make_float2(ar * inv, -aiv * inv);
        const float2* Bv = (const float2*)Bmat;
        const float2* Cv = (const float2*)Cmat;
        float2 bc = cmulf(Bv[h * NH + n], Cv[h * NH + n]);
        float2 c2 = cmulf(cmulf(bc, num), ia);
        prm[n] = make_float4(dre, dim, c2.x, c2.y);
    }
    __syncthreads();

    float acc[2][8][4];
    #pragma unroll
    for (int mt = 0; mt < 2; mt++)
        #pragma unroll
        for (int nt = 0; nt < 8; nt++)
            #pragma unroll
            for (int r = 0; r < 4; r++) acc[mt][nt][r] = 0.0f;

    #pragma unroll 1
    for (int ks = 0; ks < 4; ks++) {
        u32 ahi[2][4], alo[2][4], bhi[2][8], blo[2][8];
        #pragma unroll
        for (int mh = 0; mh < 2; mh++) {
            const int n = 8 * ks + t + 4 * mh;
            const float4 p = prm[n];

            // ---- A (G) rows a_i = 32*wid + g + 8*i, l = 64*a ----
            {
                float la = (float)((32 * wid + g) * 64);
                float sn, cs; redsc(p.y * la, &sn, &cs);
                float mg = __expf(p.x * la);          // dre*l <= 0 -> mg <= 1
                float zr = mg * cs, zi = mg * sn;
                float cr = fmaf(p.z, zr, -p.w * zi);  // G = 2Ceff * w^l
                float ci = fmaf(p.z, zi,  p.w * zr);
                float ss, sc2; redsc(p.y * 512.0f, &ss, &sc2);
                float smg = __expf(p.x * 512.0f);     // w^512 row step
                float wr = smg * sc2, wi = smg * ss;
                #pragma unroll
                for (int i = 0; i < 4; i++) {
                    float rr, ri;
                    ahi[mh][i] = pack_split(cr, -ci, rr, ri);  // (Re, -Im)
                    alo[mh][i] = pack_only(rr, ri);
                    float nr = fmaf(cr, wr, -ci * wi);
                    float ni = fmaf(cr, wi,  ci * wr);
                    cr = nr; ci = ni;
                }
            }
            // ---- B (V) cols b_j = g + 8*j ----
            {
                float lb = (float)g;
                float sn, cs; redsc(p.y * lb, &sn, &cs);
                float mg = __expf(p.x * lb);
                float vr = mg * cs, vi = mg * sn;     // V = w^b
                float ss, sc2; redsc(p.y * 8.0f, &ss, &sc2);
                float smg = __expf(p.x * 8.0f);       // w^8 col step
                float wr = smg * sc2, wi = smg * ss;
                #pragma unroll
                for (int j = 0; j < 8; j++) {
                    float rr, ri;
                    bhi[mh][j] = pack_split(vr, vi, rr, ri);   // (Re, Im)
                    blo[mh][j] = pack_only(rr, ri);
                    float nr = fmaf(vr, wr, -vi * wi);
                    float ni = fmaf(vr, wi,  vi * wr);
                    vr = nr; vi = ni;
                }
            }
        }
        // ---- 48 MMAs: 2 m-tiles x 8 n-tiles x 3 split terms ----
        #pragma unroll
        for (int mt = 0; mt < 2; mt++) {
            #pragma unroll
            for (int nt = 0; nt < 8; nt++) {
                mma_bf16(acc[mt][nt],
                         ahi[0][2 * mt], ahi[0][2 * mt + 1],
                         ahi[1][2 * mt], ahi[1][2 * mt + 1],
                         bhi[0][nt], bhi[1][nt]);              // G1*V1
                mma_bf16(acc[mt][nt],
                         ahi[0][2 * mt], ahi[0][2 * mt + 1],
                         ahi[1][2 * mt], ahi[1][2 * mt + 1],
                         blo[0][nt], blo[1][nt]);              // G1*V2
                mma_bf16(acc[mt][nt],
                         alo[0][2 * mt], alo[0][2 * mt + 1],
                         alo[1][2 * mt], alo[1][2 * mt + 1],
                         bhi[0][nt], bhi[1][nt]);              // G2*V1
            }
        }
    }

    // ---- store: D[a][b] -> out[h, 64a + b] (float2 per fragment row) ----
    float* ob = out + h * LL;
    #pragma unroll
    for (int mt = 0; mt < 2; mt++) {
        const int a0r = 32 * wid + 16 * mt + g;
        #pragma unroll
        for (int nt = 0; nt < 8; nt++) {
            const int bc = 8 * nt + 2 * t;
            *(float2*)(ob + a0r * 64 + bc) =
                make_float2(acc[mt][nt][0], acc[mt][nt][1]);
            *(float2*)(ob + (a0r + 8) * 64 + bc) =
                make_float2(acc[mt][nt][2], acc[mt][nt][3]);
        }
    }
}

extern "C" void kernel_launch(void* const* d_in, const int* in_sizes, int n_in,
                              void* d_out, int out_size)
{
    const float* log_dt     = (const float*)d_in[0];
    const float* log_A_real = (const float*)d_in[1];
    const float* A_imag     = (const float*)d_in[2];
    const float* Bmat       = (const float*)d_in[3];
    const float* Cmat       = (const float*)d_in[4];
    float* out = (float*)d_out;

    s4_mma_kernel<<<HH, 128>>>(log_dt, log_A_real, A_imag, Bmat, Cmat, out);
}